// round 6
// baseline (speedup 1.0000x reference)
#include <cuda_runtime.h>
#include <math.h>

#define LAMDA 0.1f
#define T_AVG 8192
#define THREADS 512
#define BLOCKS (148 * 2)
#define NWARPS (THREADS / 32)

// Accumulators: zero at module load; reset by the last block each launch,
// so every graph replay starts clean. Counter self-wraps via atomicInc.
__device__ float g_acc0;
__device__ float g_acc1;
__device__ unsigned int g_count;

__device__ __forceinline__ float sq4(float4 a, float4 b) {
    float d0 = a.x - b.x;
    float d1 = a.y - b.y;
    float d2 = a.z - b.z;
    float d3 = a.w - b.w;
    return d0 * d0 + d1 * d1 + d2 * d2 + d3 * d3;
}

__global__ void __launch_bounds__(THREADS, 2) fused_loss_kernel(
    const float4* __restrict__ in,
    const float4* __restrict__ tg,
    float* __restrict__ out,
    int n4, int lim4 /* = n4 - T/4 */, int chunk,
    float inv_n, int nSteps)
{
    float s_mse = 0.0f;
    float s_cyc = 0.0f;
    const int t4 = T_AVG / 4;

    // Per-block contiguous tile. Block stride = 512 float4 = 8KB per stream.
    // The c-read (i + 32KB) first-touches a line; the a-front reaches it
    // 4 iterations later. Reuse window = 3 streams x 32KB = 96KB/CTA,
    // 2 CTAs/SM -> 192KB < 228KB L1: the a-read hits L1, not L2.
    const int base = blockIdx.x * chunk;
    const int end = min(base + chunk, n4);
    const int end_cyc = min(end, lim4);
    int i = base + threadIdx.x;

    // Main 4x-unrolled path (both terms, 12 front-batched LDG.128s).
    for (; i + 3 * THREADS < end_cyc; i += 4 * THREADS) {
        float4 a0 = in[i];
        float4 a1 = in[i + THREADS];
        float4 a2 = in[i + 2 * THREADS];
        float4 a3 = in[i + 3 * THREADS];
        float4 c0 = in[i + t4];
        float4 c1 = in[i + THREADS + t4];
        float4 c2 = in[i + 2 * THREADS + t4];
        float4 c3 = in[i + 3 * THREADS + t4];
        float4 b0 = __ldcs(&tg[i]);
        float4 b1 = __ldcs(&tg[i + THREADS]);
        float4 b2 = __ldcs(&tg[i + 2 * THREADS]);
        float4 b3 = __ldcs(&tg[i + 3 * THREADS]);
        s_mse += sq4(a0, b0);
        s_mse += sq4(a1, b1);
        s_mse += sq4(a2, b2);
        s_mse += sq4(a3, b3);
        s_cyc += sq4(a0, c0);
        s_cyc += sq4(a1, c1);
        s_cyc += sq4(a2, c2);
        s_cyc += sq4(a3, c3);
    }
    // Tail of the cyc region.
    for (; i < end_cyc; i += THREADS) {
        float4 a = in[i];
        float4 b = __ldcs(&tg[i]);
        float4 c = in[i + t4];
        s_mse += sq4(a, b);
        s_cyc += sq4(a, c);
    }
    // MSE-only region (last T elements; only the final block(s) see this).
    for (; i < end; i += THREADS) {
        float4 a = in[i];
        float4 b = __ldcs(&tg[i]);
        s_mse += sq4(a, b);
    }

    // Warp reduction
    #pragma unroll
    for (int off = 16; off > 0; off >>= 1) {
        s_mse += __shfl_xor_sync(0xffffffffu, s_mse, off);
        s_cyc += __shfl_xor_sync(0xffffffffu, s_cyc, off);
    }

    __shared__ float sm_mse[NWARPS];
    __shared__ float sm_cyc[NWARPS];
    int wid = threadIdx.x >> 5;
    int lid = threadIdx.x & 31;
    if (lid == 0) {
        sm_mse[wid] = s_mse;
        sm_cyc[wid] = s_cyc;
    }
    __syncthreads();

    if (threadIdx.x == 0) {
        float bm = sm_mse[0];
        float bc = sm_cyc[0];
        #pragma unroll
        for (int w = 1; w < NWARPS; w++) {
            bm += sm_mse[w];
            bc += sm_cyc[w];
        }
        atomicAdd(&g_acc0, bm);
        atomicAdd(&g_acc1, bc);
        __threadfence();
        // atomicInc wraps to 0 when old == gridDim.x-1 -> self-resetting counter
        unsigned int ticket = atomicInc(&g_count, gridDim.x - 1);
        if (ticket == gridDim.x - 1) {
            float tot_mse = atomicAdd(&g_acc0, 0.0f);
            float tot_cyc = atomicAdd(&g_acc1, 0.0f);
            float l1 = (nSteps != 1) ? (LAMDA * sqrtf(tot_cyc)) : 0.0f;
            out[0] = tot_mse * inv_n + l1;
            // Reset for next graph replay.
            g_acc0 = 0.0f;
            g_acc1 = 0.0f;
        }
    }
}

extern "C" void kernel_launch(void* const* d_in, const int* in_sizes, int n_in,
                              void* d_out, int out_size) {
    const float* input  = (const float*)d_in[0];
    const float* target = (const float*)d_in[1];
    float* out = (float*)d_out;

    int n = in_sizes[0];         // 16,777,216
    int n4 = n / 4;
    int T = T_AVG;               // 8192 (fixed for this problem)
    int nSteps = n / T;          // 2048
    int lim4 = n4 - T / 4;       // (N-1)*T / 4

    // Contiguous per-block chunk, rounded up to the block stride so every
    // block except the last iterates uniformly.
    int chunk = (n4 + BLOCKS - 1) / BLOCKS;
    chunk = (chunk + THREADS - 1) / THREADS * THREADS;

    fused_loss_kernel<<<BLOCKS, THREADS>>>(
        (const float4*)input, (const float4*)target, out,
        n4, lim4, chunk, 1.0f / (float)n, nSteps);
}